// round 4
// baseline (speedup 1.0000x reference)
#include <cuda_runtime.h>
#include <math.h>

#define BB   8
#define NN   512
#define TT   64
#define NI   64
#define NE   128
#define NHID 128

// ---------------- device scratch (module globals; no allocations) ----------------
__device__ __align__(16) float g_An[BB*NN*NN];        // 8.4 MB normalized adjacency
__device__ __align__(16) float g_dinv[BB*NN];
__device__ __align__(16) float g_es[BB*NN*NE];        // 2 MB
__device__ __align__(16) float g_G0[BB*NN*512];       // 8.4 MB constant gate preact
__device__ __align__(16) float g_U[256*512];          // folded [Wpe@Wxbot ; Whh] 512 KB
__device__ __align__(16) float g_bias2[512];
__device__ __align__(16) float g_h[2][BB*NN*NHID];    // ping-pong hidden
__device__ __align__(16) float g_c[BB*NN*NHID];
__device__ __align__(16) float g_Xi[BB*NN*NI];

// ---------------- prep kernels ----------------

__global__ void k_dinv(const float* __restrict__ A) {
    int bn = blockIdx.x;
    const float* row = A + (size_t)bn * NN;
    float s = 0.f;
    for (int i = threadIdx.x; i < NN; i += 128) s += row[i];
    #pragma unroll
    for (int o = 16; o; o >>= 1) s += __shfl_down_sync(0xffffffffu, s, o);
    __shared__ float wsum[4];
    if ((threadIdx.x & 31) == 0) wsum[threadIdx.x >> 5] = s;
    __syncthreads();
    if (threadIdx.x == 0) {
        float d = wsum[0] + wsum[1] + wsum[2] + wsum[3];
        g_dinv[bn] = (d > 0.f) ? (1.f / sqrtf(d)) : 0.f;
    }
}

__global__ void k_An(const float* __restrict__ A) {
    int idx = blockIdx.x * 512 + threadIdx.x;   // BB*NN*NN total
    int bn = idx >> 9;
    int m  = idx & 511;
    int b  = bn >> 9;
    g_An[idx] = A[idx] * g_dinv[bn] * g_dinv[(b << 9) | m];
}

// bias2[g*128+j] = b_ig[j] + b_hg[j] + sum_l bpe[l]*Wx_g[128+l][j]
__global__ void k_bias2(const float* Wii, const float* Wif, const float* Wig, const float* Wio,
                        const float* bii, const float* bhi, const float* bif, const float* bhf,
                        const float* big, const float* bhg, const float* bio, const float* bho,
                        const float* bpe) {
    int gj = threadIdx.x;
    int g = gj >> 7, j = gj & 127;
    const float* Wx = (g == 0) ? Wii : (g == 1) ? Wif : (g == 2) ? Wig : Wio;
    const float* bi = (g == 0) ? bii : (g == 1) ? bif : (g == 2) ? big : bio;
    const float* bh = (g == 0) ? bhi : (g == 1) ? bhf : (g == 2) ? bhg : bho;
    float s = bi[j] + bh[j];
    for (int l = 0; l < 128; l++) s += bpe[l] * Wx[(128 + l) * 128 + j];
    g_bias2[gj] = s;
}

// U[k][g*128+j]: k<128 -> sum_l Wpe[k][l]*Wx_g[128+l][j];  k>=128 -> Wh_g[k-128][j]
__global__ void k_U(const float* Wpe,
                    const float* Wii, const float* Wif, const float* Wig, const float* Wio,
                    const float* Whi, const float* Whf, const float* Whg, const float* Who) {
    int idx = blockIdx.x * 256 + threadIdx.x;   // 256*512
    int k = idx >> 9;
    int gj = idx & 511;
    int g = gj >> 7, j = gj & 127;
    if (k < 128) {
        const float* Wx = (g == 0) ? Wii : (g == 1) ? Wif : (g == 2) ? Wig : Wio;
        float s = 0.f;
        for (int l = 0; l < 128; l++) s += Wpe[k * 128 + l] * Wx[(128 + l) * 128 + j];
        g_U[idx] = s;
    } else {
        const float* Wh = (g == 0) ? Whi : (g == 1) ? Whf : (g == 2) ? Whg : Who;
        g_U[idx] = Wh[(k - 128) * 128 + j];
    }
}

// es[bn][e] = X0[bn] @ Wse + bse
__global__ void k_es(const float* __restrict__ X, const float* __restrict__ Wse,
                     const float* __restrict__ bse) {
    int idx = blockIdx.x * 256 + threadIdx.x;   // BB*NN*NE
    int bn = idx >> 7, e = idx & 127;
    const float* x0 = X + (size_t)bn * TT * NI;  // t=0 row
    float s = bse[e];
    for (int k = 0; k < NI; k++) s += x0[k] * Wse[k * 128 + e];
    g_es[idx] = s;
}

// G0[bn][g*128+j] = es[bn] @ Wx_g_top + bias2.  8 rows per block for W reuse.
__global__ void k_G0(const float* Wii, const float* Wif, const float* Wig, const float* Wio) {
    __shared__ float es_s[8][128];
    int bn0 = blockIdx.x * 8;
    for (int i = threadIdx.x; i < 8 * 128; i += 512)
        es_s[i >> 7][i & 127] = g_es[(size_t)bn0 * 128 + i];
    __syncthreads();
    int gj = threadIdx.x;
    int g = gj >> 7, j = gj & 127;
    const float* Wx = (g == 0) ? Wii : (g == 1) ? Wif : (g == 2) ? Wig : Wio;
    float s[8];
    float b2 = g_bias2[gj];
    #pragma unroll
    for (int r = 0; r < 8; r++) s[r] = b2;
    for (int k = 0; k < 128; k++) {
        float w = Wx[k * 128 + j];
        #pragma unroll
        for (int r = 0; r < 8; r++) s[r] += es_s[r][k] * w;
    }
    #pragma unroll
    for (int r = 0; r < 8; r++) g_G0[(size_t)(bn0 + r) * 512 + gj] = s[r];
}

__global__ void k_init(const float* __restrict__ X, float* __restrict__ out) {
    for (int idx = blockIdx.x * blockDim.x + threadIdx.x; idx < BB * NN * NHID;
         idx += gridDim.x * blockDim.x) {
        g_h[0][idx] = 0.f;
        g_c[idx]    = 0.f;
        if (idx < BB * NN * NI) {
            int bn = idx >> 6, k = idx & 63;
            float v = X[(size_t)bn * (TT * NI) + k];
            g_Xi[idx] = v;
            out[(size_t)bn * (TT * NI) + k] = v;  // t = 0
        }
    }
}

// ---------------- step kernel: 16 rows per block, 256 threads ----------------
__global__ void __launch_bounds__(256) k_step(int t, const float* __restrict__ Wout,
                                              const float* __restrict__ bout,
                                              float* __restrict__ out) {
    __shared__ float smem_a[4608];      // phase1: hs[32][128]+as[16][32]; phase2: us; phase3: ws
    __shared__ float HH[16][264];       // [H | h_prev] per row, padded stride

    const int tid = threadIdx.x;
    const int tx = tid & 31, ty = tid >> 5;             // ty 0..7
    const int b  = blockIdx.x >> 5;
    const int r0 = (blockIdx.x & 31) << 4;

    const float* hp = g_h[(t - 1) & 1] + (size_t)b * NN * NHID;
    float*       hn = g_h[t & 1] + (size_t)b * NN * NHID;
    const float* Anb = g_An + ((size_t)b * NN + r0) * NN;

    // ---- phase 1: H[16][128] = An_rows @ h_prev (K=512, 32-chunks) ----
    float acc[2][4];
    #pragma unroll
    for (int r = 0; r < 2; r++)
        #pragma unroll
        for (int c = 0; c < 4; c++) acc[r][c] = 0.f;

    float* hs = smem_a;               // [32][128]
    float* as = smem_a + 4096;        // [16][32]

    for (int ch = 0; ch < 16; ch++) {
        int m0 = ch << 5;
        const float4* src = (const float4*)(hp + (size_t)m0 * NHID);
        float4* dst = (float4*)hs;
        #pragma unroll
        for (int i = 0; i < 4; i++) dst[tid + i * 256] = src[tid + i * 256];
        if (tid < 128) {
            int r  = tid >> 3;
            int c4 = (tid & 7) << 2;
            *(float4*)&as[r * 32 + c4] = *(const float4*)(Anb + (size_t)r * NN + m0 + c4);
        }
        __syncthreads();
        #pragma unroll 8
        for (int mm = 0; mm < 32; mm++) {
            float4 h4 = *(float4*)&hs[mm * 128 + tx * 4];
            float a0 = as[ty * 32 + mm];
            float a1 = as[(ty + 8) * 32 + mm];
            acc[0][0] += a0 * h4.x; acc[0][1] += a0 * h4.y;
            acc[0][2] += a0 * h4.z; acc[0][3] += a0 * h4.w;
            acc[1][0] += a1 * h4.x; acc[1][1] += a1 * h4.y;
            acc[1][2] += a1 * h4.z; acc[1][3] += a1 * h4.w;
        }
        __syncthreads();
    }
    *(float4*)&HH[ty][tx * 4]     = make_float4(acc[0][0], acc[0][1], acc[0][2], acc[0][3]);
    *(float4*)&HH[ty + 8][tx * 4] = make_float4(acc[1][0], acc[1][1], acc[1][2], acc[1][3]);
    // h_prev rows -> HH[:,128:256]
    {
        const float4* hr = (const float4*)(hp + (size_t)r0 * NHID);
        #pragma unroll
        for (int i = 0; i < 2; i++) {
            int idx = tid + i * 256;         // 0..511 float4s over 16x32
            int r = idx >> 5, j4 = idx & 31;
            *(float4*)&HH[r][128 + j4 * 4] = hr[r * 32 + j4];
        }
    }
    __syncthreads();

    // ---- phase 2: P[16][512] = HH(16x256) @ U(256x512) + G0 ----
    float gacc[4][2][4];
    #pragma unroll
    for (int g = 0; g < 4; g++)
        #pragma unroll
        for (int r = 0; r < 2; r++)
            #pragma unroll
            for (int c = 0; c < 4; c++) gacc[g][r][c] = 0.f;

    float* us = smem_a;               // [32][128]
    #pragma unroll
    for (int g = 0; g < 4; g++) {
        for (int kc = 0; kc < 8; kc++) {
            #pragma unroll
            for (int i = 0; i < 4; i++) {
                int idx = tid + i * 256;     // 0..1023 float4s over 32x128
                int kk = idx >> 5, j4 = idx & 31;
                *(float4*)&us[kk * 128 + j4 * 4] =
                    *(const float4*)&g_U[(size_t)(kc * 32 + kk) * 512 + g * 128 + j4 * 4];
            }
            __syncthreads();
            #pragma unroll 8
            for (int kk = 0; kk < 32; kk++) {
                float hh0 = HH[ty][kc * 32 + kk];
                float hh1 = HH[ty + 8][kc * 32 + kk];
                float4 u4 = *(float4*)&us[kk * 128 + tx * 4];
                gacc[g][0][0] += hh0 * u4.x; gacc[g][0][1] += hh0 * u4.y;
                gacc[g][0][2] += hh0 * u4.z; gacc[g][0][3] += hh0 * u4.w;
                gacc[g][1][0] += hh1 * u4.x; gacc[g][1][1] += hh1 * u4.y;
                gacc[g][1][2] += hh1 * u4.z; gacc[g][1][3] += hh1 * u4.w;
            }
            __syncthreads();
        }
    }

    // ---- elementwise LSTM cell ----
    const float* G0r = g_G0 + ((size_t)(b * NN) + r0) * 512;
    float* cb  = g_c + ((size_t)b * NN + r0) * NHID;
    float* hnb = hn + (size_t)r0 * NHID;
    #pragma unroll
    for (int rr = 0; rr < 2; rr++) {
        int r = ty + rr * 8;
        #pragma unroll
        for (int cc = 0; cc < 4; cc++) {
            int col = tx * 4 + cc;
            float pi = gacc[0][rr][cc] + G0r[(size_t)r * 512 + col];
            float pf = gacc[1][rr][cc] + G0r[(size_t)r * 512 + 128 + col];
            float pg = gacc[2][rr][cc] + G0r[(size_t)r * 512 + 256 + col];
            float po = gacc[3][rr][cc] + G0r[(size_t)r * 512 + 384 + col];
            float iv = 1.f / (1.f + expf(-pi));
            float fv = 1.f / (1.f + expf(-pf));
            float gv = tanhf(pg);
            float ov = 1.f / (1.f + expf(-po));
            float cold = cb[r * NHID + col];
            float cnew = fv * cold + iv * gv;
            float ht = ov * tanhf(cnew);
            cb[r * NHID + col]  = cnew;
            hnb[r * NHID + col] = ht;
            HH[r][col] = ht;               // reuse for output GEMM
        }
    }
    __syncthreads();

    // ---- phase 3: Xi += h_t @ Wout + bout; write out[:, :, t, :] ----
    float oacc[4] = {0.f, 0.f, 0.f, 0.f};
    int row = tid >> 4;
    int c4  = (tid & 15) << 2;
    float* ws = smem_a;               // [32][64]
    for (int kc = 0; kc < 4; kc++) {
        #pragma unroll
        for (int i = 0; i < 2; i++) {
            int idx = tid + i * 256;   // 0..511 float4s over 32x64
            *(float4*)&ws[idx * 4] = *(const float4*)(Wout + (size_t)kc * 2048 + idx * 4);
        }
        __syncthreads();
        #pragma unroll 8
        for (int kk = 0; kk < 32; kk++) {
            float hv = HH[row][kc * 32 + kk];
            float4 w4 = *(float4*)&ws[kk * 64 + c4];
            oacc[0] += hv * w4.x; oacc[1] += hv * w4.y;
            oacc[2] += hv * w4.z; oacc[3] += hv * w4.w;
        }
        __syncthreads();
    }
    size_t rowi = (size_t)(b * NN) + r0 + row;
    float4 xi = *(float4*)(g_Xi + rowi * 64 + c4);
    float4 bo = *(const float4*)(bout + c4);
    xi.x += oacc[0] + bo.x;
    xi.y += oacc[1] + bo.y;
    xi.z += oacc[2] + bo.z;
    xi.w += oacc[3] + bo.w;
    *(float4*)(g_Xi + rowi * 64 + c4) = xi;
    *(float4*)(out + (rowi * 64 + t) * 64 + c4) = xi;
}

// ---------------- launch ----------------
extern "C" void kernel_launch(void* const* d_in, const int* in_sizes, int n_in,
                              void* d_out, int out_size) {
    const float* X    = (const float*)d_in[0];
    const float* A    = (const float*)d_in[1];
    const float* Wse  = (const float*)d_in[2];
    const float* bse  = (const float*)d_in[3];
    const float* Wpe  = (const float*)d_in[4];
    const float* bpe  = (const float*)d_in[5];
    const float* Wii  = (const float*)d_in[6];
    const float* bii  = (const float*)d_in[7];
    const float* Whi  = (const float*)d_in[8];
    const float* bhi  = (const float*)d_in[9];
    const float* Wif  = (const float*)d_in[10];
    const float* bif  = (const float*)d_in[11];
    const float* Whf  = (const float*)d_in[12];
    const float* bhf  = (const float*)d_in[13];
    const float* Wig  = (const float*)d_in[14];
    const float* big  = (const float*)d_in[15];
    const float* Whg  = (const float*)d_in[16];
    const float* bhg  = (const float*)d_in[17];
    const float* Wio  = (const float*)d_in[18];
    const float* bio  = (const float*)d_in[19];
    const float* Who  = (const float*)d_in[20];
    const float* bho  = (const float*)d_in[21];
    const float* Wout = (const float*)d_in[22];
    const float* bout = (const float*)d_in[23];
    float* out = (float*)d_out;

    k_dinv<<<BB * NN, 128>>>(A);
    k_An<<<(BB * NN * NN) / 512, 512>>>(A);
    k_bias2<<<1, 512>>>(Wii, Wif, Wig, Wio, bii, bhi, bif, bhf, big, bhg, bio, bho, bpe);
    k_U<<<(256 * 512) / 256, 256>>>(Wpe, Wii, Wif, Wig, Wio, Whi, Whf, Whg, Who);
    k_es<<<(BB * NN * NE) / 256, 256>>>(X, Wse, bse);
    k_G0<<<(BB * NN) / 8, 512>>>(Wii, Wif, Wig, Wio);
    k_init<<<512, 512>>>(X, out);

    for (int t = 1; t < TT; t++) {
        k_step<<<256, 256>>>(t, Wout, bout, out);
    }
}

// round 5
// speedup vs baseline: 3.6767x; 3.6767x over previous
#include <cuda_runtime.h>
#include <cuda_bf16.h>
#include <stdint.h>
#include <math.h>

#define BB   8
#define NN   512
#define TT   64
#define NI   64
#define NHID 128

typedef __nv_bfloat16 bf16;

// ---------------- device scratch (module globals; no allocations) ----------------
__device__ __align__(16) float g_dinv[BB*NN];
__device__ __align__(16) float g_U[256*512];
__device__ __align__(16) float g_bias2[512];
__device__ __align__(16) float g_es[BB*NN*128];
__device__ __align__(16) float g_G0[BB*NN*512];
__device__ __align__(16) bf16  g_An_hi[BB*NN*NN];
__device__ __align__(16) bf16  g_An_lo[BB*NN*NN];
__device__ __align__(16) bf16  g_UT_hi[512*256];
__device__ __align__(16) bf16  g_UT_lo[512*256];
__device__ __align__(16) bf16  g_WoT_hi[64*128];
__device__ __align__(16) bf16  g_WoT_lo[64*128];
__device__ __align__(16) bf16  g_h_hi[2][BB*NN*NHID];
__device__ __align__(16) bf16  g_h_lo[2][BB*NN*NHID];
__device__ __align__(16) bf16  g_hT_hi[2][BB*NHID*NN];
__device__ __align__(16) bf16  g_hT_lo[2][BB*NHID*NN];
__device__ __align__(16) float g_c[BB*NN*NHID];
__device__ __align__(16) float g_Xi[BB*NN*NI];

// ---------------- helpers ----------------
__device__ __forceinline__ void bsplit(float f, bf16& h, bf16& l) {
    h = __float2bfloat16_rn(f);
    l = __float2bfloat16_rn(f - __bfloat162float(h));
}
__device__ __forceinline__ uint32_t packb(bf16 a, bf16 b) {
    __nv_bfloat162 v; v.x = a; v.y = b; return *(uint32_t*)&v;
}
__device__ __forceinline__ void mma_bf16(float* c,
    uint32_t a0, uint32_t a1, uint32_t a2, uint32_t a3, uint32_t b0, uint32_t b1) {
    asm volatile("mma.sync.aligned.m16n8k16.row.col.f32.bf16.bf16.f32 "
        "{%0,%1,%2,%3}, {%4,%5,%6,%7}, {%8,%9}, {%0,%1,%2,%3};"
        : "+f"(c[0]), "+f"(c[1]), "+f"(c[2]), "+f"(c[3])
        : "r"(a0), "r"(a1), "r"(a2), "r"(a3), "r"(b0), "r"(b1));
}
#define LD32(p) (*(const uint32_t*)&(p))

// ---------------- prep kernels ----------------
__global__ void k_dinv(const float* __restrict__ A) {
    int bn = blockIdx.x;
    const float* row = A + (size_t)bn * NN;
    float s = 0.f;
    for (int i = threadIdx.x; i < NN; i += 128) s += row[i];
    #pragma unroll
    for (int o = 16; o; o >>= 1) s += __shfl_down_sync(0xffffffffu, s, o);
    __shared__ float wsum[4];
    if ((threadIdx.x & 31) == 0) wsum[threadIdx.x >> 5] = s;
    __syncthreads();
    if (threadIdx.x == 0) {
        float d = wsum[0] + wsum[1] + wsum[2] + wsum[3];
        g_dinv[bn] = (d > 0.f) ? (1.f / sqrtf(d)) : 0.f;
    }
}

__global__ void k_An16(const float* __restrict__ A) {
    int idx = blockIdx.x * 512 + threadIdx.x;
    int bn = idx >> 9, m = idx & 511, b = bn >> 9;
    float v = A[idx] * g_dinv[bn] * g_dinv[(b << 9) | m];
    bf16 h, l; bsplit(v, h, l);
    g_An_hi[idx] = h; g_An_lo[idx] = l;
}

__global__ void k_bias2(const float* Wii, const float* Wif, const float* Wig, const float* Wio,
                        const float* bii, const float* bhi, const float* bif, const float* bhf,
                        const float* big, const float* bhg, const float* bio, const float* bho,
                        const float* bpe) {
    int gj = threadIdx.x;
    int g = gj >> 7, j = gj & 127;
    const float* Wx = (g == 0) ? Wii : (g == 1) ? Wif : (g == 2) ? Wig : Wio;
    const float* bi = (g == 0) ? bii : (g == 1) ? bif : (g == 2) ? big : bio;
    const float* bh = (g == 0) ? bhi : (g == 1) ? bhf : (g == 2) ? bhg : bho;
    float s = bi[j] + bh[j];
    for (int l = 0; l < 128; l++) s += bpe[l] * Wx[(128 + l) * 128 + j];
    g_bias2[gj] = s;
}

__global__ void k_U(const float* Wpe,
                    const float* Wii, const float* Wif, const float* Wig, const float* Wio,
                    const float* Whi, const float* Whf, const float* Whg, const float* Who) {
    int idx = blockIdx.x * 256 + threadIdx.x;   // 256*512
    int k = idx >> 9, gj = idx & 511;
    int g = gj >> 7, j = gj & 127;
    if (k < 128) {
        const float* Wx = (g == 0) ? Wii : (g == 1) ? Wif : (g == 2) ? Wig : Wio;
        float s = 0.f;
        for (int l = 0; l < 128; l++) s += Wpe[k * 128 + l] * Wx[(128 + l) * 128 + j];
        g_U[idx] = s;
    } else {
        const float* Wh = (g == 0) ? Whi : (g == 1) ? Whf : (g == 2) ? Whg : Who;
        g_U[idx] = Wh[(k - 128) * 128 + j];
    }
}

// UT[n][k] = U[k][n], split hi/lo
__global__ void k_UT() {
    int idx = blockIdx.x * 256 + threadIdx.x;   // 512*256, idx = n*256 + k
    int n = idx >> 8, k = idx & 255;
    bf16 h, l; bsplit(g_U[k * 512 + n], h, l);
    g_UT_hi[idx] = h; g_UT_lo[idx] = l;
}

__global__ void k_WoT(const float* __restrict__ Wout) {
    int idx = blockIdx.x * 256 + threadIdx.x;   // 64*128, idx = n*128 + k
    int n = idx >> 7, k = idx & 127;
    bf16 h, l; bsplit(Wout[k * 64 + n], h, l);
    g_WoT_hi[idx] = h; g_WoT_lo[idx] = l;
}

__global__ void k_es(const float* __restrict__ X, const float* __restrict__ Wse,
                     const float* __restrict__ bse) {
    int idx = blockIdx.x * 256 + threadIdx.x;   // BB*NN*128
    int bn = idx >> 7, e = idx & 127;
    const float* x0 = X + (size_t)bn * TT * NI;
    float s = bse[e];
    for (int k = 0; k < NI; k++) s += x0[k] * Wse[k * 128 + e];
    g_es[idx] = s;
}

__global__ void k_G0(const float* Wii, const float* Wif, const float* Wig, const float* Wio) {
    __shared__ float es_s[8][128];
    int bn0 = blockIdx.x * 8;
    for (int i = threadIdx.x; i < 8 * 128; i += 512)
        es_s[i >> 7][i & 127] = g_es[(size_t)bn0 * 128 + i];
    __syncthreads();
    int gj = threadIdx.x;
    int g = gj >> 7, j = gj & 127;
    const float* Wx = (g == 0) ? Wii : (g == 1) ? Wif : (g == 2) ? Wig : Wio;
    float s[8];
    float b2 = g_bias2[gj];
    #pragma unroll
    for (int r = 0; r < 8; r++) s[r] = b2;
    for (int k = 0; k < 128; k++) {
        float w = Wx[k * 128 + j];
        #pragma unroll
        for (int r = 0; r < 8; r++) s[r] += es_s[r][k] * w;
    }
    #pragma unroll
    for (int r = 0; r < 8; r++) g_G0[(size_t)(bn0 + r) * 512 + gj] = s[r];
}

__global__ void k_init(const float* __restrict__ X, float* __restrict__ out) {
    bf16 z = __float2bfloat16(0.f);
    for (int idx = blockIdx.x * blockDim.x + threadIdx.x; idx < BB * NN * NHID;
         idx += gridDim.x * blockDim.x) {
        g_h_hi[0][idx] = z;  g_h_lo[0][idx] = z;
        g_hT_hi[0][idx] = z; g_hT_lo[0][idx] = z;
        g_c[idx] = 0.f;
        if (idx < BB * NN * NI) {
            int bn = idx >> 6, k = idx & 63;
            float v = X[(size_t)bn * (TT * NI) + k];
            g_Xi[idx] = v;
            out[(size_t)bn * (TT * NI) + k] = v;  // t = 0
        }
    }
}

// ---------------- step kernel ----------------
// grid 128: blockIdx = b*16 + rowtile;  32 rows per block; 256 threads (8 warps 2x4)
// smem: sHH [2][32][264] bf16 (33792 B) | sX 40960 bf16 (81920 B)
//   sX aliases: phase1 A [2][32][72] + B [2][128][72]; phase2 U [2][512][40]; phase3 W [2][64][136]
#define SMEM_BYTES ((16896 + 40960) * 2)

__global__ void __launch_bounds__(256, 1) k_step(int t, const float* __restrict__ bout,
                                                 float* __restrict__ out) {
    extern __shared__ __align__(16) bf16 smem[];
    bf16* sHH = smem;            // 2*32*264
    bf16* sX  = smem + 16896;
    bf16* sA  = sX;              // 2*32*72
    bf16* sB  = sX + 4608;       // 2*128*72
    bf16* sU  = sX;              // 2*512*40
    bf16* sW  = sX;              // 2*64*136

    const int tid  = threadIdx.x;
    const int warp = tid >> 5, lane = tid & 31;
    const int gq = lane >> 2, tg = lane & 3;
    const int wm = warp >> 2, wn = warp & 3;
    const int m0 = wm * 16;
    const int b  = blockIdx.x >> 4;
    const int r0 = (blockIdx.x & 15) << 5;
    const int rdp = (t - 1) & 1, wrp = t & 1;

    const bf16* hT_hi = g_hT_hi[rdp] + (size_t)b * NHID * NN;
    const bf16* hT_lo = g_hT_lo[rdp] + (size_t)b * NHID * NN;
    const bf16* h_hi  = g_h_hi[rdp] + ((size_t)b * NN + r0) * NHID;
    const bf16* h_lo  = g_h_lo[rdp] + ((size_t)b * NN + r0) * NHID;

    // ================= phase 1: H(32x128) = An_tile(32x512) @ h(512x128) =================
    float acc[4][4];
    #pragma unroll
    for (int j = 0; j < 4; j++)
        #pragma unroll
        for (int c = 0; c < 4; c++) acc[j][c] = 0.f;

    for (int ch = 0; ch < 8; ch++) {
        int k0 = ch << 6;
        #pragma unroll
        for (int i = 0; i < 2; i++) {            // An chunk: [2][32][64]
            int e = tid + i * 256;
            int v = e >> 8, rem = e & 255, r = rem >> 3, q = rem & 7;
            const bf16* src = (v ? g_An_lo : g_An_hi)
                              + ((size_t)(b * NN + r0 + r)) * NN + k0 + q * 8;
            *(uint4*)&sA[v * 2304 + r * 72 + q * 8] = *(const uint4*)src;
        }
        #pragma unroll
        for (int i = 0; i < 8; i++) {            // hT chunk: [2][128][64]
            int e = tid + i * 256;
            int v = e >> 10, rem = e & 1023, n = rem >> 3, q = rem & 7;
            const bf16* src = (v ? hT_lo : hT_hi) + (size_t)n * NN + k0 + q * 8;
            *(uint4*)&sB[v * 9216 + n * 72 + q * 8] = *(const uint4*)src;
        }
        __syncthreads();
        #pragma unroll
        for (int ks = 0; ks < 4; ks++) {
            int kk = ks * 16;
            int ar = (m0 + gq) * 72 + kk + 2 * tg;
            uint32_t ah0 = LD32(sA[ar]),           ah1 = LD32(sA[ar + 8 * 72]);
            uint32_t ah2 = LD32(sA[ar + 8]),       ah3 = LD32(sA[ar + 8 * 72 + 8]);
            uint32_t al0 = LD32(sA[2304 + ar]),    al1 = LD32(sA[2304 + ar + 8 * 72]);
            uint32_t al2 = LD32(sA[2304 + ar + 8]), al3 = LD32(sA[2304 + ar + 8 * 72 + 8]);
            #pragma unroll
            for (int j = 0; j < 4; j++) {
                int br = (wn * 32 + j * 8 + gq) * 72 + kk + 2 * tg;
                uint32_t bh0 = LD32(sB[br]),        bh1 = LD32(sB[br + 8]);
                uint32_t bl0 = LD32(sB[9216 + br]), bl1 = LD32(sB[9216 + br + 8]);
                mma_bf16(acc[j], ah0, ah1, ah2, ah3, bh0, bh1);
                mma_bf16(acc[j], ah0, ah1, ah2, ah3, bl0, bl1);
                mma_bf16(acc[j], al0, al1, al2, al3, bh0, bh1);
            }
        }
        __syncthreads();
    }
    // write H -> sHH[:, 0:128] as hi/lo
    #pragma unroll
    for (int j = 0; j < 4; j++) {
        int col = wn * 32 + j * 8 + 2 * tg;
        int rA = m0 + gq, rB = m0 + gq + 8;
        bf16 h0, l0, h1, l1;
        bsplit(acc[j][0], h0, l0); bsplit(acc[j][1], h1, l1);
        *(uint32_t*)&sHH[rA * 264 + col] = packb(h0, h1);
        *(uint32_t*)&sHH[8448 + rA * 264 + col] = packb(l0, l1);
        bsplit(acc[j][2], h0, l0); bsplit(acc[j][3], h1, l1);
        *(uint32_t*)&sHH[rB * 264 + col] = packb(h0, h1);
        *(uint32_t*)&sHH[8448 + rB * 264 + col] = packb(l0, l1);
    }
    // copy h tile rows -> sHH[:, 128:256]
    #pragma unroll
    for (int i = 0; i < 4; i++) {
        int e = tid + i * 256;
        int v = e >> 9, rem = e & 511, r = rem >> 4, q = rem & 15;
        const bf16* src = (v ? h_lo : h_hi) + (size_t)r * NHID + q * 8;
        *(uint4*)&sHH[v * 8448 + r * 264 + 128 + q * 8] = *(const uint4*)src;
    }
    __syncthreads();

    // ================= phase 2: P(32x512) = HH(32x256) @ U(256x512) + G0 =================
    float pacc[4][4][4];
    #pragma unroll
    for (int g4 = 0; g4 < 4; g4++)
        #pragma unroll
        for (int j = 0; j < 4; j++)
            #pragma unroll
            for (int c = 0; c < 4; c++) pacc[g4][j][c] = 0.f;

    for (int ch = 0; ch < 8; ch++) {
        int k0 = ch << 5;
        #pragma unroll
        for (int i = 0; i < 16; i++) {           // UT chunk: [2][512][32]
            int e = tid + i * 256;
            int v = e >> 11, rem = e & 2047, n = rem >> 2, q = rem & 3;
            const bf16* src = (v ? g_UT_lo : g_UT_hi) + (size_t)n * 256 + k0 + q * 8;
            *(uint4*)&sU[v * 20480 + n * 40 + q * 8] = *(const uint4*)src;
        }
        __syncthreads();
        #pragma unroll
        for (int ks = 0; ks < 2; ks++) {
            int kk = ks * 16;
            int ar = (m0 + gq) * 264 + k0 + kk + 2 * tg;
            uint32_t ah0 = LD32(sHH[ar]),            ah1 = LD32(sHH[ar + 8 * 264]);
            uint32_t ah2 = LD32(sHH[ar + 8]),        ah3 = LD32(sHH[ar + 8 * 264 + 8]);
            uint32_t al0 = LD32(sHH[8448 + ar]),     al1 = LD32(sHH[8448 + ar + 8 * 264]);
            uint32_t al2 = LD32(sHH[8448 + ar + 8]), al3 = LD32(sHH[8448 + ar + 8 * 264 + 8]);
            #pragma unroll
            for (int g4 = 0; g4 < 4; g4++) {
                #pragma unroll
                for (int j = 0; j < 4; j++) {
                    int br = (g4 * 128 + wn * 32 + j * 8 + gq) * 40 + kk + 2 * tg;
                    uint32_t bh0 = LD32(sU[br]),         bh1 = LD32(sU[br + 8]);
                    uint32_t bl0 = LD32(sU[20480 + br]), bl1 = LD32(sU[20480 + br + 8]);
                    mma_bf16(pacc[g4][j], ah0, ah1, ah2, ah3, bh0, bh1);
                    mma_bf16(pacc[g4][j], ah0, ah1, ah2, ah3, bl0, bl1);
                    mma_bf16(pacc[g4][j], al0, al1, al2, al3, bh0, bh1);
                }
            }
        }
        __syncthreads();
    }

    // ----- LSTM elementwise (results live in this thread's accum positions) -----
    {
        const float* G0r = g_G0 + ((size_t)(b * NN + r0)) * 512;
        float* crow = g_c + ((size_t)(b * NN + r0)) * NHID;
        bf16* nh_hi = g_h_hi[wrp] + ((size_t)b * NN + r0) * NHID;
        bf16* nh_lo = g_h_lo[wrp] + ((size_t)b * NN + r0) * NHID;
        bf16* nhT_hi = g_hT_hi[wrp] + (size_t)b * NHID * NN;
        bf16* nhT_lo = g_hT_lo[wrp] + (size_t)b * NHID * NN;
        #pragma unroll
        for (int rr = 0; rr < 2; rr++) {
            int r = m0 + gq + rr * 8;
            #pragma unroll
            for (int j = 0; j < 4; j++) {
                #pragma unroll
                for (int c = 0; c < 2; c++) {
                    int col = wn * 32 + j * 8 + 2 * tg + c;
                    int ai = rr * 2 + c;
                    float pi = pacc[0][j][ai] + G0r[(size_t)r * 512 + col];
                    float pf = pacc[1][j][ai] + G0r[(size_t)r * 512 + 128 + col];
                    float pg = pacc[2][j][ai] + G0r[(size_t)r * 512 + 256 + col];
                    float po = pacc[3][j][ai] + G0r[(size_t)r * 512 + 384 + col];
                    float iv = 1.f / (1.f + expf(-pi));
                    float fv = 1.f / (1.f + expf(-pf));
                    float gv = tanhf(pg);
                    float ov = 1.f / (1.f + expf(-po));
                    float cn = fv * crow[r * NHID + col] + iv * gv;
                    float ht = ov * tanhf(cn);
                    crow[r * NHID + col] = cn;
                    bf16 hh, hl; bsplit(ht, hh, hl);
                    nh_hi[r * NHID + col] = hh;
                    nh_lo[r * NHID + col] = hl;
                    nhT_hi[(size_t)col * NN + r0 + r] = hh;
                    nhT_lo[(size_t)col * NN + r0 + r] = hl;
                    sHH[r * 264 + col] = hh;
                    sHH[8448 + r * 264 + col] = hl;
                }
            }
        }
    }
    // stage WoutT into smem
    #pragma unroll
    for (int i = 0; i < 8; i++) {
        int e = tid + i * 256;
        int v = e >> 10, rem = e & 1023, n = rem >> 4, q = rem & 15;
        const bf16* src = (v ? g_WoT_lo : g_WoT_hi) + (size_t)n * 128 + q * 8;
        *(uint4*)&sW[v * 8704 + n * 136 + q * 8] = *(const uint4*)src;
    }
    __syncthreads();

    // ================= phase 3: O(32x64) = h_t(32x128) @ Wout(128x64) =================
    float oacc[2][4];
    #pragma unroll
    for (int j = 0; j < 2; j++)
        #pragma unroll
        for (int c = 0; c < 4; c++) oacc[j][c] = 0.f;

    #pragma unroll
    for (int ks = 0; ks < 8; ks++) {
        int kk = ks * 16;
        int ar = (m0 + gq) * 264 + kk + 2 * tg;
        uint32_t ah0 = LD32(sHH[ar]),            ah1 = LD32(sHH[ar + 8 * 264]);
        uint32_t ah2 = LD32(sHH[ar + 8]),        ah3 = LD32(sHH[ar + 8 * 264 + 8]);
        uint32_t al0 = LD32(sHH[8448 + ar]),     al1 = LD32(sHH[8448 + ar + 8 * 264]);
        uint32_t al2 = LD32(sHH[8448 + ar + 8]), al3 = LD32(sHH[8448 + ar + 8 * 264 + 8]);
        #pragma unroll
        for (int j = 0; j < 2; j++) {
            int br = (wn * 16 + j * 8 + gq) * 136 + kk + 2 * tg;
            uint32_t bh0 = LD32(sW[br]),        bh1 = LD32(sW[br + 8]);
            uint32_t bl0 = LD32(sW[8704 + br]), bl1 = LD32(sW[8704 + br + 8]);
            mma_bf16(oacc[j], ah0, ah1, ah2, ah3, bh0, bh1);
            mma_bf16(oacc[j], ah0, ah1, ah2, ah3, bl0, bl1);
            mma_bf16(oacc[j], al0, al1, al2, al3, bh0, bh1);
        }
    }
    #pragma unroll
    for (int rr = 0; rr < 2; rr++) {
        int r = m0 + gq + rr * 8;
        size_t bn = (size_t)(b * NN) + r0 + r;
        #pragma unroll
        for (int j = 0; j < 2; j++) {
            #pragma unroll
            for (int c = 0; c < 2; c++) {
                int col = wn * 16 + j * 8 + 2 * tg + c;
                float v = oacc[j][rr * 2 + c] + bout[col] + g_Xi[bn * 64 + col];
                g_Xi[bn * 64 + col] = v;
                out[(bn * 64 + t) * 64 + col] = v;
            }
        }
    }
}

// ---------------- launch ----------------
extern "C" void kernel_launch(void* const* d_in, const int* in_sizes, int n_in,
                              void* d_out, int out_size) {
    const float* X    = (const float*)d_in[0];
    const float* A    = (const float*)d_in[1];
    const float* Wse  = (const float*)d_in[2];
    const float* bse  = (const float*)d_in[3];
    const float* Wpe  = (const float*)d_in[4];
    const float* bpe  = (const float*)d_in[5];
    const float* Wii  = (const float*)d_in[6];
    const float* bii  = (const float*)d_in[7];
    const float* Whi  = (const float*)d_in[8];
    const float* bhi  = (const float*)d_in[9];
    const float* Wif  = (const float*)d_in[10];
    const float* bif  = (const float*)d_in[11];
    const float* Whf  = (const float*)d_in[12];
    const float* bhf  = (const float*)d_in[13];
    const float* Wig  = (const float*)d_in[14];
    const float* big  = (const float*)d_in[15];
    const float* Whg  = (const float*)d_in[16];
    const float* bhg  = (const float*)d_in[17];
    const float* Wio  = (const float*)d_in[18];
    const float* bio  = (const float*)d_in[19];
    const float* Who  = (const float*)d_in[20];
    const float* bho  = (const float*)d_in[21];
    const float* Wout = (const float*)d_in[22];
    const float* bout = (const float*)d_in[23];
    float* out = (float*)d_out;

    cudaFuncSetAttribute(k_step, cudaFuncAttributeMaxDynamicSharedMemorySize, SMEM_BYTES);

    k_dinv<<<BB * NN, 128>>>(A);
    k_An16<<<(BB * NN * NN) / 512, 512>>>(A);
    k_bias2<<<1, 512>>>(Wii, Wif, Wig, Wio, bii, bhi, bif, bhf, big, bhg, bio, bho, bpe);
    k_U<<<512, 256>>>(Wpe, Wii, Wif, Wig, Wio, Whi, Whf, Whg, Who);
    k_UT<<<512, 256>>>();
    k_WoT<<<32, 256>>>(Wout);
    k_es<<<(BB * NN * 128) / 256, 256>>>(X, Wse, bse);
    k_G0<<<(BB * NN) / 8, 512>>>(Wii, Wif, Wig, Wio);
    k_init<<<512, 512>>>(X, out);

    for (int t = 1; t < TT; t++) {
        k_step<<<128, 256, SMEM_BYTES>>>(t, bout, out);
    }
}

// round 7
// speedup vs baseline: 3.9720x; 1.0803x over previous
#include <cuda_runtime.h>
#include <cuda_bf16.h>
#include <stdint.h>
#include <math.h>

#define BB   8
#define NN   512
#define TT   64
#define NI   64
#define NHID 128

typedef __nv_bfloat16 bf16;

// ---------------- device scratch (module globals; no allocations) ----------------
__device__ __align__(16) float g_dinv[BB*NN];
__device__ __align__(16) float g_U[256*512];
__device__ __align__(16) float g_bias2[512];
__device__ __align__(16) float g_es[BB*NN*128];
__device__ __align__(16) float g_G0[BB*NN*512];
__device__ __align__(16) bf16  g_An_hi[BB*NN*NN];
__device__ __align__(16) bf16  g_An_lo[BB*NN*NN];
__device__ __align__(16) bf16  g_UT_hi[512*256];
__device__ __align__(16) bf16  g_UT_lo[512*256];
__device__ __align__(16) bf16  g_WoT_hi[64*128];
__device__ __align__(16) bf16  g_WoT_lo[64*128];
__device__ __align__(16) bf16  g_h_hi[2][BB*NN*NHID];
__device__ __align__(16) bf16  g_h_lo[2][BB*NN*NHID];
__device__ __align__(16) bf16  g_hT_hi[2][BB*NHID*NN];
__device__ __align__(16) bf16  g_hT_lo[2][BB*NHID*NN];
__device__ __align__(16) float g_c[BB*NN*NHID];
__device__ __align__(16) float g_Xi[BB*NN*NI];

// ---------------- helpers ----------------
__device__ __forceinline__ void bsplit(float f, bf16& h, bf16& l) {
    h = __float2bfloat16_rn(f);
    l = __float2bfloat16_rn(f - __bfloat162float(h));
}
__device__ __forceinline__ uint32_t packb(bf16 a, bf16 b) {
    __nv_bfloat162 v; v.x = a; v.y = b; return *(uint32_t*)&v;
}
__device__ __forceinline__ void mma_bf16(float* c,
    uint32_t a0, uint32_t a1, uint32_t a2, uint32_t a3, uint32_t b0, uint32_t b1) {
    asm volatile("mma.sync.aligned.m16n8k16.row.col.f32.bf16.bf16.f32 "
        "{%0,%1,%2,%3}, {%4,%5,%6,%7}, {%8,%9}, {%0,%1,%2,%3};"
        : "+f"(c[0]), "+f"(c[1]), "+f"(c[2]), "+f"(c[3])
        : "r"(a0), "r"(a1), "r"(a2), "r"(a3), "r"(b0), "r"(b1));
}
__device__ __forceinline__ void cpa16(uint32_t dst, const void* src) {
    asm volatile("cp.async.cg.shared.global [%0], [%1], 16;" :: "r"(dst), "l"(src) : "memory");
}
#define CP_COMMIT asm volatile("cp.async.commit_group;" ::: "memory")
#define CP_WAIT0  asm volatile("cp.async.wait_group 0;" ::: "memory")
#define LD32(p) (*(const uint32_t*)&(p))

// ---------------- prep kernels ----------------
__global__ void k_dinv(const float* __restrict__ A) {
    int bn = blockIdx.x;
    const float* row = A + (size_t)bn * NN;
    float s = 0.f;
    for (int i = threadIdx.x; i < NN; i += 128) s += row[i];
    #pragma unroll
    for (int o = 16; o; o >>= 1) s += __shfl_down_sync(0xffffffffu, s, o);
    __shared__ float wsum[4];
    if ((threadIdx.x & 31) == 0) wsum[threadIdx.x >> 5] = s;
    __syncthreads();
    if (threadIdx.x == 0) {
        float d = wsum[0] + wsum[1] + wsum[2] + wsum[3];
        g_dinv[bn] = (d > 0.f) ? (1.f / sqrtf(d)) : 0.f;
    }
}

__global__ void k_An16(const float* __restrict__ A) {
    int idx = blockIdx.x * 512 + threadIdx.x;
    int bn = idx >> 9, m = idx & 511, b = bn >> 9;
    float v = A[idx] * g_dinv[bn] * g_dinv[(b << 9) | m];
    bf16 h, l; bsplit(v, h, l);
    g_An_hi[idx] = h; g_An_lo[idx] = l;
}

__global__ void k_bias2(const float* Wii, const float* Wif, const float* Wig, const float* Wio,
                        const float* bii, const float* bhi, const float* bif, const float* bhf,
                        const float* big, const float* bhg, const float* bio, const float* bho,
                        const float* bpe) {
    int gj = threadIdx.x;
    int g = gj >> 7, j = gj & 127;
    const float* Wx = (g == 0) ? Wii : (g == 1) ? Wif : (g == 2) ? Wig : Wio;
    const float* bi = (g == 0) ? bii : (g == 1) ? bif : (g == 2) ? big : bio;
    const float* bh = (g == 0) ? bhi : (g == 1) ? bhf : (g == 2) ? bhg : bho;
    float s = bi[j] + bh[j];
    for (int l = 0; l < 128; l++) s += bpe[l] * Wx[(128 + l) * 128 + j];
    g_bias2[gj] = s;
}

__global__ void k_U(const float* Wpe,
                    const float* Wii, const float* Wif, const float* Wig, const float* Wio,
                    const float* Whi, const float* Whf, const float* Whg, const float* Who) {
    int idx = blockIdx.x * 256 + threadIdx.x;   // 256*512
    int k = idx >> 9, gj = idx & 511;
    int g = gj >> 7, j = gj & 127;
    if (k < 128) {
        const float* Wx = (g == 0) ? Wii : (g == 1) ? Wif : (g == 2) ? Wig : Wio;
        float s = 0.f;
        for (int l = 0; l < 128; l++) s += Wpe[k * 128 + l] * Wx[(128 + l) * 128 + j];
        g_U[idx] = s;
    } else {
        const float* Wh = (g == 0) ? Whi : (g == 1) ? Whf : (g == 2) ? Whg : Who;
        g_U[idx] = Wh[(k - 128) * 128 + j];
    }
}

// UT[n][k] = U[k][n], split hi/lo
__global__ void k_UT() {
    int idx = blockIdx.x * 256 + threadIdx.x;   // 512*256, idx = n*256 + k
    int n = idx >> 8, k = idx & 255;
    bf16 h, l; bsplit(g_U[k * 512 + n], h, l);
    g_UT_hi[idx] = h; g_UT_lo[idx] = l;
}

__global__ void k_WoT(const float* __restrict__ Wout) {
    int idx = blockIdx.x * 256 + threadIdx.x;   // 64*128, idx = n*128 + k
    int n = idx >> 7, k = idx & 127;
    bf16 h, l; bsplit(Wout[k * 64 + n], h, l);
    g_WoT_hi[idx] = h; g_WoT_lo[idx] = l;
}

__global__ void k_es(const float* __restrict__ X, const float* __restrict__ Wse,
                     const float* __restrict__ bse) {
    int idx = blockIdx.x * 256 + threadIdx.x;   // BB*NN*128
    int bn = idx >> 7, e = idx & 127;
    const float* x0 = X + (size_t)bn * TT * NI;
    float s = bse[e];
    for (int k = 0; k < NI; k++) s += x0[k] * Wse[k * 128 + e];
    g_es[idx] = s;
}

__global__ void k_G0(const float* Wii, const float* Wif, const float* Wig, const float* Wio) {
    __shared__ float es_s[8][128];
    int bn0 = blockIdx.x * 8;
    for (int i = threadIdx.x; i < 8 * 128; i += 512)
        es_s[i >> 7][i & 127] = g_es[(size_t)bn0 * 128 + i];
    __syncthreads();
    int gj = threadIdx.x;
    int g = gj >> 7, j = gj & 127;
    const float* Wx = (g == 0) ? Wii : (g == 1) ? Wif : (g == 2) ? Wig : Wio;
    float s[8];
    float b2 = g_bias2[gj];
    #pragma unroll
    for (int r = 0; r < 8; r++) s[r] = b2;
    for (int k = 0; k < 128; k++) {
        float w = Wx[k * 128 + j];
        #pragma unroll
        for (int r = 0; r < 8; r++) s[r] += es_s[r][k] * w;
    }
    #pragma unroll
    for (int r = 0; r < 8; r++) g_G0[(size_t)(bn0 + r) * 512 + gj] = s[r];
}

__global__ void k_init(const float* __restrict__ X, float* __restrict__ out) {
    bf16 z = __float2bfloat16(0.f);
    for (int idx = blockIdx.x * blockDim.x + threadIdx.x; idx < BB * NN * NHID;
         idx += gridDim.x * blockDim.x) {
        g_h_hi[0][idx] = z;  g_h_lo[0][idx] = z;
        g_hT_hi[0][idx] = z; g_hT_lo[0][idx] = z;
        g_c[idx] = 0.f;
        if (idx < BB * NN * NI) {
            int bn = idx >> 6, k = idx & 63;
            float v = X[(size_t)bn * (TT * NI) + k];
            g_Xi[idx] = v;
            out[(size_t)bn * (TT * NI) + k] = v;  // t = 0
        }
    }
}

// ---------------- step kernel ----------------
// grid 128: blockIdx = b*16 + rowtile; 32 rows/block; 256 threads (8 warps 2x4)
// smem elems (bf16): sHH [2][32][264] = 16896 at 0; staging region 87040 at 16896.
//   Phase1: stage s at s*23040  -> sA [2][32][72] (+0), sB [2][128][72] (+4608)
//   Phase2: even ch at 46080, odd ch at 0 -> sU [2][512][40] (40960 elems)
//   Phase3: sW [2][64][136] (17408 elems) at 46080
#define SMEM_BYTES ((16896 + 87040) * 2)

__global__ void __launch_bounds__(256, 1) k_step(int t, const float* __restrict__ bout,
                                                 float* __restrict__ out) {
    extern __shared__ __align__(16) bf16 smem[];
    bf16* sHH = smem;                    // 16896 elems
    bf16* STG = smem + 16896;
    const uint32_t stg_u = (uint32_t)__cvta_generic_to_shared(STG);

    const int tid  = threadIdx.x;
    const int warp = tid >> 5, lane = tid & 31;
    const int gq = lane >> 2, tg = lane & 3;
    const int wm = warp >> 2, wn = warp & 3;
    const int m0 = wm * 16;
    const int b  = blockIdx.x >> 4;
    const int r0 = (blockIdx.x & 15) << 5;
    const int rdp = (t - 1) & 1, wrp = t & 1;

    const bf16* hT_hi = g_hT_hi[rdp] + (size_t)b * NHID * NN;
    const bf16* hT_lo = g_hT_lo[rdp] + (size_t)b * NHID * NN;
    const bf16* h_hi  = g_h_hi[rdp] + ((size_t)b * NN + r0) * NHID;
    const bf16* h_lo  = g_h_lo[rdp] + ((size_t)b * NN + r0) * NHID;

    // ---- prefetchers ----
    auto pf1 = [&](int ch) {
        int s = ch & 1, k0 = ch << 6;
        uint32_t base = stg_u + (uint32_t)(s * 23040) * 2;
        #pragma unroll
        for (int i = 0; i < 2; i++) {            // An chunk: [2][32][64]
            int e = tid + i * 256;
            int v = e >> 8, rem = e & 255, r = rem >> 3, q = rem & 7;
            const bf16* src = (v ? g_An_lo : g_An_hi)
                              + ((size_t)(b * NN + r0 + r)) * NN + k0 + q * 8;
            cpa16(base + (uint32_t)(v * 2304 + r * 72 + q * 8) * 2, src);
        }
        #pragma unroll
        for (int i = 0; i < 8; i++) {            // hT chunk: [2][128][64]
            int e = tid + i * 256;
            int v = e >> 10, rem = e & 1023, n = rem >> 3, q = rem & 7;
            const bf16* src = (v ? hT_lo : hT_hi) + (size_t)n * NN + k0 + q * 8;
            cpa16(base + (uint32_t)(4608 + v * 9216 + n * 72 + q * 8) * 2, src);
        }
        CP_COMMIT;
    };
    auto pf2 = [&](int ch) {
        int k0 = ch << 5;
        uint32_t base = stg_u + (uint32_t)((ch & 1) ? 0 : 46080) * 2;
        #pragma unroll
        for (int i = 0; i < 16; i++) {           // UT chunk: [2][512][32]
            int e = tid + i * 256;
            int v = e >> 11, rem = e & 2047, n = rem >> 2, q = rem & 3;
            const bf16* src = (v ? g_UT_lo : g_UT_hi) + (size_t)n * 256 + k0 + q * 8;
            cpa16(base + (uint32_t)(v * 20480 + n * 40 + q * 8) * 2, src);
        }
        CP_COMMIT;
    };
    auto pf3 = [&]() {
        uint32_t base = stg_u + 46080u * 2;
        #pragma unroll
        for (int i = 0; i < 8; i++) {            // WoT: [2][64][128]
            int e = tid + i * 256;
            int v = e >> 10, rem = e & 1023, n = rem >> 4, q = rem & 15;
            const bf16* src = (v ? g_WoT_lo : g_WoT_hi) + (size_t)n * 128 + q * 8;
            cpa16(base + (uint32_t)(v * 8704 + n * 136 + q * 8) * 2, src);
        }
        CP_COMMIT;
    };

    // ================= phase 1: H(32x128) = An_tile(32x512) @ h(512x128) =================
    float acc[4][4];
    #pragma unroll
    for (int j = 0; j < 4; j++)
        #pragma unroll
        for (int c = 0; c < 4; c++) acc[j][c] = 0.f;

    pf1(0);
    for (int ch = 0; ch < 8; ch++) {
        CP_WAIT0;
        __syncthreads();
        if (ch < 7) pf1(ch + 1);
        else        pf2(0);                       // phase-2 chunk0 -> region 46080 (disjoint)
        const bf16* sA = STG + (ch & 1) * 23040;
        const bf16* sB = sA + 4608;
        #pragma unroll
        for (int ks = 0; ks < 4; ks++) {
            int kk = ks * 16;
            int ar = (m0 + gq) * 72 + kk + 2 * tg;
            uint32_t ah0 = LD32(sA[ar]),            ah1 = LD32(sA[ar + 8 * 72]);
            uint32_t ah2 = LD32(sA[ar + 8]),        ah3 = LD32(sA[ar + 8 * 72 + 8]);
            uint32_t al0 = LD32(sA[2304 + ar]),     al1 = LD32(sA[2304 + ar + 8 * 72]);
            uint32_t al2 = LD32(sA[2304 + ar + 8]), al3 = LD32(sA[2304 + ar + 8 * 72 + 8]);
            #pragma unroll
            for (int j = 0; j < 4; j++) {
                int br = (wn * 32 + j * 8 + gq) * 72 + kk + 2 * tg;
                uint32_t bh0 = LD32(sB[br]),        bh1 = LD32(sB[br + 8]);
                uint32_t bl0 = LD32(sB[9216 + br]), bl1 = LD32(sB[9216 + br + 8]);
                mma_bf16(acc[j], ah0, ah1, ah2, ah3, bh0, bh1);
                mma_bf16(acc[j], ah0, ah1, ah2, ah3, bl0, bl1);
                mma_bf16(acc[j], al0, al1, al2, al3, bh0, bh1);
            }
        }
        __syncthreads();
    }
    // write H -> sHH[:, 0:128] as hi/lo
    #pragma unroll
    for (int j = 0; j < 4; j++) {
        int col = wn * 32 + j * 8 + 2 * tg;
        int rA = m0 + gq, rB = m0 + gq + 8;
        bf16 h0, l0, h1, l1;
        bsplit(acc[j][0], h0, l0); bsplit(acc[j][1], h1, l1);
        *(uint32_t*)&sHH[rA * 264 + col] = packb(h0, h1);
        *(uint32_t*)&sHH[8448 + rA * 264 + col] = packb(l0, l1);
        bsplit(acc[j][2], h0, l0); bsplit(acc[j][3], h1, l1);
        *(uint32_t*)&sHH[rB * 264 + col] = packb(h0, h1);
        *(uint32_t*)&sHH[8448 + rB * 264 + col] = packb(l0, l1);
    }
    // copy h tile rows -> sHH[:, 128:256]
    #pragma unroll
    for (int i = 0; i < 4; i++) {
        int e = tid + i * 256;
        int v = e >> 9, rem = e & 511, r = rem >> 4, q = rem & 15;
        const bf16* src = (v ? h_lo : h_hi) + (size_t)r * NHID + q * 8;
        *(uint4*)&sHH[v * 8448 + r * 264 + 128 + q * 8] = *(const uint4*)src;
    }

    // ================= phase 2: P(32x512) = HH(32x256) @ U(256x512) + G0 =================
    float pacc[4][4][4];
    #pragma unroll
    for (int g4 = 0; g4 < 4; g4++)
        #pragma unroll
        for (int j = 0; j < 4; j++)
            #pragma unroll
            for (int c = 0; c < 4; c++) pacc[g4][j][c] = 0.f;

    for (int ch = 0; ch < 8; ch++) {
        CP_WAIT0;
        __syncthreads();                          // iter0 also publishes sHH writes
        if (ch < 7) pf2(ch + 1);
        else        pf3();                        // WoT -> region 46080 (chunk6's stage, drained)
        const bf16* sU = STG + ((ch & 1) ? 0 : 46080);
        int k0 = ch << 5;
        #pragma unroll
        for (int ks = 0; ks < 2; ks++) {
            int kk = ks * 16;
            int ar = (m0 + gq) * 264 + k0 + kk + 2 * tg;
            uint32_t ah0 = LD32(sHH[ar]),            ah1 = LD32(sHH[ar + 8 * 264]);
            uint32_t ah2 = LD32(sHH[ar + 8]),        ah3 = LD32(sHH[ar + 8 * 264 + 8]);
            uint32_t al0 = LD32(sHH[8448 + ar]),     al1 = LD32(sHH[8448 + ar + 8 * 264]);
            uint32_t al2 = LD32(sHH[8448 + ar + 8]), al3 = LD32(sHH[8448 + ar + 8 * 264 + 8]);
            #pragma unroll
            for (int g4 = 0; g4 < 4; g4++) {
                #pragma unroll
                for (int j = 0; j < 4; j++) {
                    int br = (g4 * 128 + wn * 32 + j * 8 + gq) * 40 + kk + 2 * tg;
                    uint32_t bh0 = LD32(sU[br]),         bh1 = LD32(sU[br + 8]);
                    uint32_t bl0 = LD32(sU[20480 + br]), bl1 = LD32(sU[20480 + br + 8]);
                    mma_bf16(pacc[g4][j], ah0, ah1, ah2, ah3, bh0, bh1);
                    mma_bf16(pacc[g4][j], ah0, ah1, ah2, ah3, bl0, bl1);
                    mma_bf16(pacc[g4][j], al0, al1, al2, al3, bh0, bh1);
                }
            }
        }
        __syncthreads();
    }

    // ----- LSTM elementwise (writes sHH cols<128 only; slowest warps read cols 224..255) -----
    {
        const float* G0r = g_G0 + ((size_t)(b * NN + r0)) * 512;
        float* crow = g_c + ((size_t)(b * NN + r0)) * NHID;
        bf16* nh_hi = g_h_hi[wrp] + ((size_t)b * NN + r0) * NHID;
        bf16* nh_lo = g_h_lo[wrp] + ((size_t)b * NN + r0) * NHID;
        bf16* nhT_hi = g_hT_hi[wrp] + (size_t)b * NHID * NN;
        bf16* nhT_lo = g_hT_lo[wrp] + (size_t)b * NHID * NN;
        #pragma unroll
        for (int rr = 0; rr < 2; rr++) {
            int r = m0 + gq + rr * 8;
            #pragma unroll
            for (int j = 0; j < 4; j++) {
                #pragma unroll
                for (int c = 0; c < 2; c++) {
                    int col = wn * 32 + j * 8 + 2 * tg + c;
                    int ai = rr * 2 + c;
                    float pi = pacc[0][j][ai] + G0r[(size_t)r * 512 + col];
                    float pf = pacc[1][j][ai] + G0r[(size_t)r * 512 + 128 + col];
                    float pg = pacc[2][j][ai] + G0r[(size_t)r * 512 + 256 + col];
                    float po = pacc[3][j][ai] + G0r[(size_t)r * 512 + 384 + col];
                    float iv = 1.f / (1.f + expf(-pi));
                    float fv = 1.f / (1.f + expf(-pf));
                    float gv = tanhf(pg);
                    float ov = 1.f / (1.f + expf(-po));
                    float cn = fv * crow[r * NHID + col] + iv * gv;
                    float ht = ov * tanhf(cn);
                    crow[r * NHID + col] = cn;
                    bf16 hh, hl; bsplit(ht, hh, hl);
                    nh_hi[r * NHID + col] = hh;
                    nh_lo[r * NHID + col] = hl;
                    nhT_hi[(size_t)col * NN + r0 + r] = hh;
                    nhT_lo[(size_t)col * NN + r0 + r] = hl;
                    sHH[r * 264 + col] = hh;
                    sHH[8448 + r * 264 + col] = hl;
                }
            }
        }
    }
    CP_WAIT0;           // WoT landed
    __syncthreads();    // + all h_t writes to sHH visible

    // ================= phase 3: O(32x64) = h_t(32x128) @ Wout(128x64) =================
    const bf16* sW = STG + 46080;
    float oacc[2][4];
    #pragma unroll
    for (int j = 0; j < 2; j++)
        #pragma unroll
        for (int c = 0; c < 4; c++) oacc[j][c] = 0.f;

    #pragma unroll
    for (int ks = 0; ks < 8; ks++) {
        int kk = ks * 16;
        int ar = (m0 + gq) * 264 + kk + 2 * tg;
        uint32_t ah0 = LD32(sHH[ar]),            ah1 = LD32(sHH[ar + 8 * 264]);
        uint32_t ah2 = LD32(sHH[ar + 8]),        ah3 = LD32(sHH[ar + 8 * 264 + 8]);
        uint32_t al0 = LD32(sHH[8448 + ar]),     al1 = LD32(sHH[8448 + ar + 8 * 264]);
        uint32_t al2 = LD32(sHH[8448 + ar + 8]), al3 = LD32(sHH[8448 + ar + 8 * 264 + 8]);
        #pragma unroll
        for (int j = 0; j < 2; j++) {
            int br = (wn * 16 + j * 8 + gq) * 136 + kk + 2 * tg;
            uint32_t bh0 = LD32(sW[br]),        bh1 = LD32(sW[br + 8]);
            uint32_t bl0 = LD32(sW[8704 + br]), bl1 = LD32(sW[8704 + br + 8]);
            mma_bf16(oacc[j], ah0, ah1, ah2, ah3, bh0, bh1);
            mma_bf16(oacc[j], ah0, ah1, ah2, ah3, bl0, bl1);
            mma_bf16(oacc[j], al0, al1, al2, al3, bh0, bh1);
        }
    }
    #pragma unroll
    for (int rr = 0; rr < 2; rr++) {
        int r = m0 + gq + rr * 8;
        size_t bn = (size_t)(b * NN) + r0 + r;
        #pragma unroll
        for (int j = 0; j < 2; j++) {
            #pragma unroll
            for (int c = 0; c < 2; c++) {
                int col = wn * 16 + j * 8 + 2 * tg + c;
                float v = oacc[j][rr * 2 + c] + bout[col] + g_Xi[bn * 64 + col];
                g_Xi[bn * 64 + col] = v;
                out[(bn * 64 + t) * 64 + col] = v;
            }
        }
    }
}

// ---------------- launch ----------------
extern "C" void kernel_launch(void* const* d_in, const int* in_sizes, int n_in,
                              void* d_out, int out_size) {
    const float* X    = (const float*)d_in[0];
    const float* A    = (const float*)d_in[1];
    const float* Wse  = (const float*)d_in[2];
    const float* bse  = (const float*)d_in[3];
    const float* Wpe  = (const float*)d_in[4];
    const float* bpe  = (const float*)d_in[5];
    const float* Wii  = (const float*)d_in[6];
    const float* bii  = (const float*)d_in[7];
    const float* Whi  = (const float*)d_in[8];
    const float* bhi  = (const float*)d_in[9];
    const float* Wif  = (const float*)d_in[10];
    const float* bif  = (const float*)d_in[11];
    const float* Whf  = (const float*)d_in[12];
    const float* bhf  = (const float*)d_in[13];
    const float* Wig  = (const float*)d_in[14];
    const float* big  = (const float*)d_in[15];
    const float* Whg  = (const float*)d_in[16];
    const float* bhg  = (const float*)d_in[17];
    const float* Wio  = (const float*)d_in[18];
    const float* bio  = (const float*)d_in[19];
    const float* Who  = (const float*)d_in[20];
    const float* bho  = (const float*)d_in[21];
    const float* Wout = (const float*)d_in[22];
    const float* bout = (const float*)d_in[23];
    float* out = (float*)d_out;

    cudaFuncSetAttribute(k_step, cudaFuncAttributeMaxDynamicSharedMemorySize, SMEM_BYTES);

    k_dinv<<<BB * NN, 128>>>(A);
    k_An16<<<(BB * NN * NN) / 512, 512>>>(A);
    k_bias2<<<1, 512>>>(Wii, Wif, Wig, Wio, bii, bhi, bif, bhf, big, bhg, bio, bho, bpe);
    k_U<<<512, 256>>>(Wpe, Wii, Wif, Wig, Wio, Whi, Whf, Whg, Who);
    k_UT<<<512, 256>>>();
    k_WoT<<<32, 256>>>(Wout);
    k_es<<<(BB * NN * 128) / 256, 256>>>(X, Wse, bse);
    k_G0<<<(BB * NN) / 8, 512>>>(Wii, Wif, Wig, Wio);
    k_init<<<512, 512>>>(X, out);

    for (int t = 1; t < TT; t++) {
        k_step<<<128, 256, SMEM_BYTES>>>(t, bout, out);
    }
}